// round 8
// baseline (speedup 1.0000x reference)
#include <cuda_runtime.h>
#include <cstdint>

#define B_  32
#define C_  128
#define L_  256
#define CC_ (C_ * C_)      // 16384
#define BCC_ (B_ * CC_)    // 524288

// Scratch (device globals — no allocations allowed)
__device__ float g_diff[BCC_];        // [b][i][j] pairwise L1
__device__ float g_tmpS[BCC_];        // exp(relu((1-diffn)*a))
__device__ float g_y[B_ * C_ * L_];   // adj^T x  (column-normalized)
__device__ float g_tt[256 * 512];     // B operand: [n][k] K-major, sign-folded

// ===========================================================================
// helpers
// ===========================================================================
__device__ __forceinline__ float tf32_hi(float v) {
    return __uint_as_float(__float_as_uint(v) & 0xFFFFE000u);
}
__device__ __forceinline__ float cvt_tf32(float v) {
    uint32_t r;
    asm("cvt.rna.tf32.f32 %0, %1;" : "=r"(r) : "f"(v));
    return __uint_as_float(r);
}
__device__ __forceinline__ void mma_16n8k8(float c[4], const uint32_t a[4],
                                           const uint32_t b[2]) {
    asm volatile(
        "mma.sync.aligned.m16n8k8.row.col.f32.tf32.tf32.f32 "
        "{%0,%1,%2,%3}, {%4,%5,%6,%7}, {%8,%9}, {%0,%1,%2,%3};"
        : "+f"(c[0]), "+f"(c[1]), "+f"(c[2]), "+f"(c[3])
        : "r"(a[0]), "r"(a[1]), "r"(a[2]), "r"(a[3]), "r"(b[0]), "r"(b[1]));
}

// ---------------------------------------------------------------------------
// Kernel A (merged): blockIdx.x < 36  -> symmetric pairwise-L1 diff tile
//                    blockIdx.x >= 36 -> Theta transpose/sign-fold into g_tt
// grid (40, 32), 256 threads.
// ---------------------------------------------------------------------------
__global__ void __launch_bounds__(256) k_ttdiff(const float* __restrict__ x,
                                                const float* __restrict__ Theta) {
    __shared__ float sxi[16][260];
    __shared__ float sxj[16][260];

    if (blockIdx.x >= 36) {
        __shared__ float t[32][33];
        const int id = (blockIdx.x - 36) * 32 + blockIdx.y;   // 0..127
        const int kt = (id >> 3) * 32, nt = (id & 7) * 32;
        const int tx = threadIdx.x & 31, ty = threadIdx.x >> 5;  // ty 0..7
#pragma unroll
        for (int r = 0; r < 32; r += 8) {
            int k = kt + ty + r;
            int n = nt + tx;
            float v = (k < 256) ? Theta[k * 256 + n]
                                : -Theta[65536 + (k - 256) * 256 + n];
            t[ty + r][tx] = v;
        }
        __syncthreads();
#pragma unroll
        for (int r = 0; r < 32; r += 8) {
            int n = nt + ty + r;
            int k = kt + tx;
            g_tt[n * 512 + k] = t[tx][ty + r];
        }
        return;
    }

    const int b = blockIdx.y;
    int rem = blockIdx.x, ti = 0;
    while (rem >= 8 - ti) { rem -= 8 - ti; ti++; }
    const int tj = ti + rem;
    const int i0 = ti * 16, j0 = tj * 16;

    const int tid = threadIdx.x;
    const float* xb = x + b * C_ * L_;

#pragma unroll
    for (int rep = 0; rep < 4; rep++) {
        int idx = rep * 256 + tid;
        int row = idx >> 6, c4 = (idx & 63) * 4;
        *reinterpret_cast<float4*>(&sxi[row][c4]) =
            *reinterpret_cast<const float4*>(xb + (i0 + row) * L_ + c4);
        *reinterpret_cast<float4*>(&sxj[row][c4]) =
            *reinterpret_cast<const float4*>(xb + (j0 + row) * L_ + c4);
    }
    __syncthreads();

    const int ii = tid >> 4, jj = tid & 15;
    const float* ri = &sxi[ii][0];
    const float* rj = &sxj[jj][0];

    float a0 = 0.f, a1 = 0.f, a2 = 0.f, a3 = 0.f;
#pragma unroll
    for (int l = 0; l < L_; l += 16) {
        float4 u0 = *reinterpret_cast<const float4*>(ri + l);
        float4 v0 = *reinterpret_cast<const float4*>(rj + l);
        float4 u1 = *reinterpret_cast<const float4*>(ri + l + 4);
        float4 v1 = *reinterpret_cast<const float4*>(rj + l + 4);
        float4 u2 = *reinterpret_cast<const float4*>(ri + l + 8);
        float4 v2 = *reinterpret_cast<const float4*>(rj + l + 8);
        float4 u3 = *reinterpret_cast<const float4*>(ri + l + 12);
        float4 v3 = *reinterpret_cast<const float4*>(rj + l + 12);
        a0 += fabsf(u0.x - v0.x) + fabsf(u0.y - v0.y)
            + fabsf(u0.z - v0.z) + fabsf(u0.w - v0.w);
        a1 += fabsf(u1.x - v1.x) + fabsf(u1.y - v1.y)
            + fabsf(u1.z - v1.z) + fabsf(u1.w - v1.w);
        a2 += fabsf(u2.x - v2.x) + fabsf(u2.y - v2.y)
            + fabsf(u2.z - v2.z) + fabsf(u2.w - v2.w);
        a3 += fabsf(u3.x - v3.x) + fabsf(u3.y - v3.y)
            + fabsf(u3.z - v3.z) + fabsf(u3.w - v3.w);
    }
    float res = (a0 + a1) + (a2 + a3);

    g_diff[b * CC_ + (i0 + ii) * C_ + (j0 + jj)] = res;
    if (ti != tj)
        g_diff[b * CC_ + (j0 + jj) * C_ + (i0 + ii)] = res;
}

// ---------------------------------------------------------------------------
// Kernel B (fused norm+tmps, fully elementwise): thread per (i,j) pair.
// ---------------------------------------------------------------------------
__global__ void __launch_bounds__(128) k_nt(const float* __restrict__ a) {
    const int ij = blockIdx.x * 128 + threadIdx.x;

    float d[B_];
#pragma unroll
    for (int b = 0; b < B_; b++) d[b] = g_diff[b * CC_ + ij];

    float ss = 0.f;
#pragma unroll
    for (int b = 0; b < B_; b++) ss += d[b] * d[b];
    const float rn  = 1.f / fmaxf(sqrtf(ss), 1e-12f);
    const float aij = a[ij];

#pragma unroll
    for (int b = 0; b < B_; b++) {
        float v = __expf(fmaxf((1.f - d[b] * rn) * aij, 0.f));
        g_tmpS[b * CC_ + ij] = v;
    }
}

// ---------------------------------------------------------------------------
// Kernel C: y[b,j,l] = (1/cs[b,j]) * sum_i tmpS[b,i,j] * x[b,i,l]
// Column sums computed in-kernel. grid (4 l, 4 j, 32 b), 128 threads.
// ---------------------------------------------------------------------------
__global__ void k_y(const float* __restrict__ x) {
    __shared__ float sS[16][32];
    __shared__ float sX[16][64];
    __shared__ float srcs[32];
    const int b  = blockIdx.z;
    const int j0 = blockIdx.y * 32;
    const int l0 = blockIdx.x * 64;
    const int tid = threadIdx.x;
    const int tx = tid & 15, ty = tid >> 4;  // ty 0..7

    float acc[4][4];
#pragma unroll
    for (int r = 0; r < 4; r++)
#pragma unroll
        for (int c = 0; c < 4; c++) acc[r][c] = 0.f;
    float csum = 0.f;

    const float* Sb = g_tmpS + b * CC_;
    const float* Xb = x + b * C_ * L_;

#pragma unroll 1
    for (int i0 = 0; i0 < C_; i0 += 16) {
        __syncthreads();
#pragma unroll
        for (int rep = 0; rep < 4; rep++) {
            int idx = rep * 128 + tid;
            int r = idx >> 5, c = idx & 31;
            sS[r][c] = Sb[(i0 + r) * C_ + j0 + c];
        }
#pragma unroll
        for (int rep = 0; rep < 8; rep++) {
            int idx = rep * 128 + tid;
            int r = idx >> 6, c = idx & 63;
            sX[r][c] = Xb[(i0 + r) * L_ + l0 + c];
        }
        __syncthreads();
        if (tid < 32) {
#pragma unroll
            for (int r = 0; r < 16; r++) csum += sS[r][tid];
        }
#pragma unroll
        for (int i = 0; i < 16; i++) {
            float4 av = *reinterpret_cast<const float4*>(&sS[i][ty * 4]);
            float4 bv = *reinterpret_cast<const float4*>(&sX[i][tx * 4]);
            float a4[4] = {av.x, av.y, av.z, av.w};
            float b4[4] = {bv.x, bv.y, bv.z, bv.w};
#pragma unroll
            for (int r = 0; r < 4; r++)
#pragma unroll
                for (int c = 0; c < 4; c++)
                    acc[r][c] += a4[r] * b4[c];
        }
    }
    if (tid < 32) srcs[tid] = 1.f / csum;
    __syncthreads();

#pragma unroll
    for (int r = 0; r < 4; r++) {
        int jj = j0 + ty * 4 + r;
        float rc = srcs[ty * 4 + r];
        float4 v = make_float4(acc[r][0] * rc, acc[r][1] * rc,
                               acc[r][2] * rc, acc[r][3] * rc);
        *reinterpret_cast<float4*>(&g_y[b * C_ * L_ + jj * L_ + l0 + tx * 4]) = v;
    }
}

// ---------------------------------------------------------------------------
// Kernel D (tensor core, mma.sync tf32, 3-pass hi/lo split, SW-pipelined):
//   out = relu( [x | g_y] @ g_tt^T ),  M=4096, N=256, K=512
// CTA: 64x64 tile, 256 threads (8 warps in 2m x 4n, warp tile 32x16).
// smem stores hi/lo INTERLEAVED ([row][2c]=hi,[2c+1]=lo, stride 76 floats =
// 304 bytes, 16B-multiple so float4 stores are aligned) -> one LDS.64 fetches
// the hi+lo fragment pair. grid (4 n, 64 m) = 256 CTAs; next slab prefetched.
// ---------------------------------------------------------------------------
#define SSTRIDE 76

__global__ void __launch_bounds__(256) k_out_mma(const float* __restrict__ x,
                                                 float* __restrict__ out) {
    __shared__ float sA[64][SSTRIDE];
    __shared__ float sB[64][SSTRIDE];

    const int tid  = threadIdx.x;
    const int lane = tid & 31, wid = tid >> 5;   // 8 warps
    const int n0 = blockIdx.x * 64;
    const int r0 = blockIdx.y * 64;
    const int wm = (wid >> 2) * 32;   // 0 or 32
    const int wn = (wid & 3) * 16;    // 0,16,32,48
    const int qr = lane >> 2;         // 0..7
    const int qc = lane & 3;          // 0..3
    const int prow = tid >> 3, pc4 = (tid & 7) * 4;  // 32 rows x 8 col4 per pass

    float acc[2][2][4];
#pragma unroll
    for (int mi = 0; mi < 2; mi++)
#pragma unroll
        for (int ni = 0; ni < 2; ni++)
#pragma unroll
            for (int e = 0; e < 4; e++) acc[mi][ni][e] = 0.f;

    // prefetch slab 0
    float4 pA[2], pB[2];
    {
        const float* Asrc = x + (size_t)r0 * L_;
        const float* Bsrc = g_tt + (size_t)n0 * 512;
#pragma unroll
        for (int it = 0; it < 2; it++) {
            pA[it] = *reinterpret_cast<const float4*>(Asrc + (prow + it * 32) * L_ + pc4);
            pB[it] = *reinterpret_cast<const float4*>(Bsrc + (prow + it * 32) * 512 + pc4);
        }
    }

#pragma unroll 1
    for (int s = 0; s < 16; s++) {
        __syncthreads();
        // hand current slab to smem, hi/lo interleaved
#pragma unroll
        for (int it = 0; it < 2; it++) {
            int row = prow + it * 32;
            float4 v = pA[it];
            float hx = tf32_hi(v.x), hy = tf32_hi(v.y), hz = tf32_hi(v.z), hw = tf32_hi(v.w);
            float4 p0 = make_float4(hx, cvt_tf32(v.x - hx), hy, cvt_tf32(v.y - hy));
            float4 p1 = make_float4(hz, cvt_tf32(v.z - hz), hw, cvt_tf32(v.w - hw));
            *reinterpret_cast<float4*>(&sA[row][pc4 * 2])     = p0;
            *reinterpret_cast<float4*>(&sA[row][pc4 * 2 + 4]) = p1;

            float4 w = pB[it];
            float gx = tf32_hi(w.x), gy = tf32_hi(w.y), gz = tf32_hi(w.z), gw = tf32_hi(w.w);
            float4 q0 = make_float4(gx, cvt_tf32(w.x - gx), gy, cvt_tf32(w.y - gy));
            float4 q1 = make_float4(gz, cvt_tf32(w.z - gz), gw, cvt_tf32(w.w - gw));
            *reinterpret_cast<float4*>(&sB[row][pc4 * 2])     = q0;
            *reinterpret_cast<float4*>(&sB[row][pc4 * 2 + 4]) = q1;
        }
        __syncthreads();

        // prefetch next slab (overlaps MMA work below)
        if (s < 15) {
            const int sn = s + 1;
            const float* Asrc = (sn < 8) ? (x   + (size_t)r0 * L_ + sn * 32)
                                         : (g_y + (size_t)r0 * L_ + (sn - 8) * 32);
            const float* Bsrc = g_tt + (size_t)n0 * 512 + sn * 32;
#pragma unroll
            for (int it = 0; it < 2; it++) {
                pA[it] = *reinterpret_cast<const float4*>(Asrc + (prow + it * 32) * L_ + pc4);
                pB[it] = *reinterpret_cast<const float4*>(Bsrc + (prow + it * 32) * 512 + pc4);
            }
        }

#pragma unroll
        for (int k8 = 0; k8 < 4; k8++) {
            const int k = k8 * 8;
            uint32_t ah[2][4], al[2][4], bh[2][2], bl[2][2];
#pragma unroll
            for (int mi = 0; mi < 2; mi++) {
                int r = wm + mi * 16 + qr;
                float2 a0 = *reinterpret_cast<const float2*>(&sA[r    ][(k + qc) * 2]);
                float2 a1 = *reinterpret_cast<const float2*>(&sA[r + 8][(k + qc) * 2]);
                float2 a2 = *reinterpret_cast<const float2*>(&sA[r    ][(k + qc + 4) * 2]);
                float2 a3 = *reinterpret_cast<const float2*>(&sA[r + 8][(k + qc + 4) * 2]);
                ah[mi][0] = __float_as_uint(a0.x);  al[mi][0] = __float_as_uint(a0.y);
                ah[mi][1] = __float_as_uint(a1.x);  al[mi][1] = __float_as_uint(a1.y);
                ah[mi][2] = __float_as_uint(a2.x);  al[mi][2] = __float_as_uint(a2.y);
                ah[mi][3] = __float_as_uint(a3.x);  al[mi][3] = __float_as_uint(a3.y);
            }
#pragma unroll
            for (int ni = 0; ni < 2; ni++) {
                int n = wn + ni * 8 + qr;
                float2 b0 = *reinterpret_cast<const float2*>(&sB[n][(k + qc) * 2]);
                float2 b1 = *reinterpret_cast<const float2*>(&sB[n][(k + qc + 4) * 2]);
                bh[ni][0] = __float_as_uint(b0.x);  bl[ni][0] = __float_as_uint(b0.y);
                bh[ni][1] = __float_as_uint(b1.x);  bl[ni][1] = __float_as_uint(b1.y);
            }
#pragma unroll
            for (int mi = 0; mi < 2; mi++)
#pragma unroll
                for (int ni = 0; ni < 2; ni++)
                    mma_16n8k8(acc[mi][ni], ah[mi], bh[ni]);
#pragma unroll
            for (int mi = 0; mi < 2; mi++)
#pragma unroll
                for (int ni = 0; ni < 2; ni++)
                    mma_16n8k8(acc[mi][ni], al[mi], bh[ni]);
#pragma unroll
            for (int mi = 0; mi < 2; mi++)
#pragma unroll
                for (int ni = 0; ni < 2; ni++)
                    mma_16n8k8(acc[mi][ni], ah[mi], bl[ni]);
        }
    }

#pragma unroll
    for (int mi = 0; mi < 2; mi++) {
        int row = r0 + wm + mi * 16 + qr;
#pragma unroll
        for (int ni = 0; ni < 2; ni++) {
            int col = n0 + wn + ni * 8 + qc * 2;
            float2 v0 = make_float2(fmaxf(acc[mi][ni][0], 0.f),
                                    fmaxf(acc[mi][ni][1], 0.f));
            float2 v1 = make_float2(fmaxf(acc[mi][ni][2], 0.f),
                                    fmaxf(acc[mi][ni][3], 0.f));
            *reinterpret_cast<float2*>(out + (size_t)row * L_ + col) = v0;
            *reinterpret_cast<float2*>(out + (size_t)(row + 8) * L_ + col) = v1;
        }
    }
}

// ---------------------------------------------------------------------------
extern "C" void kernel_launch(void* const* d_in, const int* in_sizes, int n_in,
                              void* d_out, int out_size) {
    const float* x     = (const float*)d_in[0];   // [32,128,256]
    const float* a     = (const float*)d_in[1];   // [128,128]
    const float* Theta = (const float*)d_in[2];   // [2,256,256]
    float* out = (float*)d_out;                   // [32,128,256]

    k_ttdiff <<<dim3(40, 32),   256>>>(x, Theta);
    k_nt     <<<128,            128>>>(a);
    k_y      <<<dim3(4, 4, 32), 128>>>(x);
    k_out_mma<<<dim3(4, 64),    256>>>(x, out);
}

// round 9
// speedup vs baseline: 1.2309x; 1.2309x over previous
#include <cuda_runtime.h>
#include <cstdint>

#define B_  32
#define C_  128
#define L_  256
#define CC_ (C_ * C_)      // 16384
#define BCC_ (B_ * CC_)    // 524288
#define MOUT (4096 * 256)  // flattened out elems

// Scratch (device globals — no allocations allowed)
__device__ float g_diff[BCC_];        // [b][i][j] pairwise L1
__device__ float g_tmpS[BCC_];        // exp(relu((1-diffn)*a))
__device__ float g_y[B_ * C_ * L_];   // adj^T x  (column-normalized)
__device__ float g_tt[256 * 512];     // B operand: [n][k] K-major, sign-folded
__device__ float g_part[2][MOUT];     // K-split GEMM partials

// ===========================================================================
// helpers
// ===========================================================================
__device__ __forceinline__ float tf32_hi(float v) {
    return __uint_as_float(__float_as_uint(v) & 0xFFFFE000u);
}
__device__ __forceinline__ float cvt_tf32(float v) {
    uint32_t r;
    asm("cvt.rna.tf32.f32 %0, %1;" : "=r"(r) : "f"(v));
    return __uint_as_float(r);
}
__device__ __forceinline__ void mma_16n8k8(float c[4], const uint32_t a[4],
                                           const uint32_t b[2]) {
    asm volatile(
        "mma.sync.aligned.m16n8k8.row.col.f32.tf32.tf32.f32 "
        "{%0,%1,%2,%3}, {%4,%5,%6,%7}, {%8,%9}, {%0,%1,%2,%3};"
        : "+f"(c[0]), "+f"(c[1]), "+f"(c[2]), "+f"(c[3])
        : "r"(a[0]), "r"(a[1]), "r"(a[2]), "r"(a[3]), "r"(b[0]), "r"(b[1]));
}

// ---------------------------------------------------------------------------
// Kernel A (merged): blockIdx.x < 36  -> symmetric pairwise-L1 diff tile
//                    blockIdx.x >= 36 -> Theta transpose/sign-fold into g_tt
// grid (40, 32), 256 threads.
// ---------------------------------------------------------------------------
__global__ void __launch_bounds__(256) k_ttdiff(const float* __restrict__ x,
                                                const float* __restrict__ Theta) {
    __shared__ float sxi[16][260];
    __shared__ float sxj[16][260];

    if (blockIdx.x >= 36) {
        __shared__ float t[32][33];
        const int id = (blockIdx.x - 36) * 32 + blockIdx.y;   // 0..127
        const int kt = (id >> 3) * 32, nt = (id & 7) * 32;
        const int tx = threadIdx.x & 31, ty = threadIdx.x >> 5;  // ty 0..7
#pragma unroll
        for (int r = 0; r < 32; r += 8) {
            int k = kt + ty + r;
            int n = nt + tx;
            float v = (k < 256) ? Theta[k * 256 + n]
                                : -Theta[65536 + (k - 256) * 256 + n];
            t[ty + r][tx] = v;
        }
        __syncthreads();
#pragma unroll
        for (int r = 0; r < 32; r += 8) {
            int n = nt + ty + r;
            int k = kt + tx;
            g_tt[n * 512 + k] = t[tx][ty + r];
        }
        return;
    }

    const int b = blockIdx.y;
    int rem = blockIdx.x, ti = 0;
    while (rem >= 8 - ti) { rem -= 8 - ti; ti++; }
    const int tj = ti + rem;
    const int i0 = ti * 16, j0 = tj * 16;

    const int tid = threadIdx.x;
    const float* xb = x + b * C_ * L_;

#pragma unroll
    for (int rep = 0; rep < 4; rep++) {
        int idx = rep * 256 + tid;
        int row = idx >> 6, c4 = (idx & 63) * 4;
        *reinterpret_cast<float4*>(&sxi[row][c4]) =
            *reinterpret_cast<const float4*>(xb + (i0 + row) * L_ + c4);
        *reinterpret_cast<float4*>(&sxj[row][c4]) =
            *reinterpret_cast<const float4*>(xb + (j0 + row) * L_ + c4);
    }
    __syncthreads();

    const int ii = tid >> 4, jj = tid & 15;
    const float* ri = &sxi[ii][0];
    const float* rj = &sxj[jj][0];

    float a0 = 0.f, a1 = 0.f, a2 = 0.f, a3 = 0.f;
#pragma unroll
    for (int l = 0; l < L_; l += 16) {
        float4 u0 = *reinterpret_cast<const float4*>(ri + l);
        float4 v0 = *reinterpret_cast<const float4*>(rj + l);
        float4 u1 = *reinterpret_cast<const float4*>(ri + l + 4);
        float4 v1 = *reinterpret_cast<const float4*>(rj + l + 4);
        float4 u2 = *reinterpret_cast<const float4*>(ri + l + 8);
        float4 v2 = *reinterpret_cast<const float4*>(rj + l + 8);
        float4 u3 = *reinterpret_cast<const float4*>(ri + l + 12);
        float4 v3 = *reinterpret_cast<const float4*>(rj + l + 12);
        a0 += fabsf(u0.x - v0.x) + fabsf(u0.y - v0.y)
            + fabsf(u0.z - v0.z) + fabsf(u0.w - v0.w);
        a1 += fabsf(u1.x - v1.x) + fabsf(u1.y - v1.y)
            + fabsf(u1.z - v1.z) + fabsf(u1.w - v1.w);
        a2 += fabsf(u2.x - v2.x) + fabsf(u2.y - v2.y)
            + fabsf(u2.z - v2.z) + fabsf(u2.w - v2.w);
        a3 += fabsf(u3.x - v3.x) + fabsf(u3.y - v3.y)
            + fabsf(u3.z - v3.z) + fabsf(u3.w - v3.w);
    }
    float res = (a0 + a1) + (a2 + a3);

    g_diff[b * CC_ + (i0 + ii) * C_ + (j0 + jj)] = res;
    if (ti != tj)
        g_diff[b * CC_ + (j0 + jj) * C_ + (i0 + ii)] = res;
}

// ---------------------------------------------------------------------------
// Kernel B (fused norm+tmps): 2 threads per (i,j) pair, b split 16/16,
// shfl_xor combine for the cross-b sum of squares. grid 256 x 128 threads.
// ---------------------------------------------------------------------------
__global__ void __launch_bounds__(128) k_nt(const float* __restrict__ a) {
    const int g  = blockIdx.x * 128 + threadIdx.x;
    const int ij = g >> 1;
    const int h  = g & 1;          // which half of b
    const int b0 = h * 16;

    float d[16];
#pragma unroll
    for (int bb = 0; bb < 16; bb++) d[bb] = g_diff[(b0 + bb) * CC_ + ij];

    float ss = 0.f;
#pragma unroll
    for (int bb = 0; bb < 16; bb++) ss += d[bb] * d[bb];
    ss += __shfl_xor_sync(0xFFFFFFFFu, ss, 1);     // combine halves

    const float rn  = 1.f / fmaxf(sqrtf(ss), 1e-12f);
    const float aij = a[ij];

#pragma unroll
    for (int bb = 0; bb < 16; bb++) {
        float v = __expf(fmaxf((1.f - d[bb] * rn) * aij, 0.f));
        g_tmpS[(b0 + bb) * CC_ + ij] = v;
    }
}

// ---------------------------------------------------------------------------
// Kernel C: y[b,j,l] = (1/cs[b,j]) * sum_i tmpS[b,i,j] * x[b,i,l]
// Column sums computed in-kernel. grid (4 l, 4 j, 32 b), 128 threads.
// ---------------------------------------------------------------------------
__global__ void k_y(const float* __restrict__ x) {
    __shared__ float sS[16][32];
    __shared__ float sX[16][64];
    __shared__ float srcs[32];
    const int b  = blockIdx.z;
    const int j0 = blockIdx.y * 32;
    const int l0 = blockIdx.x * 64;
    const int tid = threadIdx.x;
    const int tx = tid & 15, ty = tid >> 4;  // ty 0..7

    float acc[4][4];
#pragma unroll
    for (int r = 0; r < 4; r++)
#pragma unroll
        for (int c = 0; c < 4; c++) acc[r][c] = 0.f;
    float csum = 0.f;

    const float* Sb = g_tmpS + b * CC_;
    const float* Xb = x + b * C_ * L_;

#pragma unroll 1
    for (int i0 = 0; i0 < C_; i0 += 16) {
        __syncthreads();
#pragma unroll
        for (int rep = 0; rep < 4; rep++) {
            int idx = rep * 128 + tid;
            int r = idx >> 5, c = idx & 31;
            sS[r][c] = Sb[(i0 + r) * C_ + j0 + c];
        }
#pragma unroll
        for (int rep = 0; rep < 8; rep++) {
            int idx = rep * 128 + tid;
            int r = idx >> 6, c = idx & 63;
            sX[r][c] = Xb[(i0 + r) * L_ + l0 + c];
        }
        __syncthreads();
        if (tid < 32) {
#pragma unroll
            for (int r = 0; r < 16; r++) csum += sS[r][tid];
        }
#pragma unroll
        for (int i = 0; i < 16; i++) {
            float4 av = *reinterpret_cast<const float4*>(&sS[i][ty * 4]);
            float4 bv = *reinterpret_cast<const float4*>(&sX[i][tx * 4]);
            float a4[4] = {av.x, av.y, av.z, av.w};
            float b4[4] = {bv.x, bv.y, bv.z, bv.w};
#pragma unroll
            for (int r = 0; r < 4; r++)
#pragma unroll
                for (int c = 0; c < 4; c++)
                    acc[r][c] += a4[r] * b4[c];
        }
    }
    if (tid < 32) srcs[tid] = 1.f / csum;
    __syncthreads();

#pragma unroll
    for (int r = 0; r < 4; r++) {
        int jj = j0 + ty * 4 + r;
        float rc = srcs[ty * 4 + r];
        float4 v = make_float4(acc[r][0] * rc, acc[r][1] * rc,
                               acc[r][2] * rc, acc[r][3] * rc);
        *reinterpret_cast<float4*>(&g_y[b * C_ * L_ + jj * L_ + l0 + tx * 4]) = v;
    }
}

// ---------------------------------------------------------------------------
// Kernel D (R6 design + K-split): partial = A_z @ B_z^T over 8 K-slabs.
//   z=0: A = x, B k-range [0,256);  z=1: A = g_y, B k-range [256,512).
// CTA: 64x64 tile, 128 threads (4 warps 2x2, warp 32x32). grid (4 n, 64 m, 2 z)
// = 512 CTAs. 3-pass tf32 hi/lo split, pad-36 smem, register prefetch.
// ---------------------------------------------------------------------------
__global__ void __launch_bounds__(128) k_out_mma(const float* __restrict__ x) {
    __shared__ float sAH[64][36], sAL[64][36];
    __shared__ float sBH[64][36], sBL[64][36];

    const int tid  = threadIdx.x;
    const int lane = tid & 31, wid = tid >> 5;
    const int n0 = blockIdx.x * 64;
    const int r0 = blockIdx.y * 64;
    const int z  = blockIdx.z;
    const int wm = (wid >> 1) * 32;
    const int wn = (wid & 1) * 32;
    const int qr = lane >> 2;
    const int qc = lane & 3;
    const int prow = tid >> 3, pc4 = (tid & 7) * 4;

    const float* Abase = z ? g_y : x;                       // [4096][256]
    const float* Bbase = g_tt + (size_t)n0 * 512 + z * 256; // k offset

    float acc[2][4][4];
#pragma unroll
    for (int mi = 0; mi < 2; mi++)
#pragma unroll
        for (int ni = 0; ni < 4; ni++)
#pragma unroll
            for (int e = 0; e < 4; e++) acc[mi][ni][e] = 0.f;

    // prefetch slab 0
    float4 pA[4], pB[4];
    {
        const float* Asrc = Abase + (size_t)r0 * L_;
#pragma unroll
        for (int it = 0; it < 4; it++) {
            pA[it] = *reinterpret_cast<const float4*>(Asrc + (prow + it * 16) * L_ + pc4);
            pB[it] = *reinterpret_cast<const float4*>(Bbase + (prow + it * 16) * 512 + pc4);
        }
    }

#pragma unroll 1
    for (int s = 0; s < 8; s++) {
        __syncthreads();
#pragma unroll
        for (int it = 0; it < 4; it++) {
            int row = prow + it * 16;
            float4 v = pA[it];
            float4 h = make_float4(tf32_hi(v.x), tf32_hi(v.y), tf32_hi(v.z), tf32_hi(v.w));
            float4 l = make_float4(cvt_tf32(v.x - h.x), cvt_tf32(v.y - h.y),
                                   cvt_tf32(v.z - h.z), cvt_tf32(v.w - h.w));
            *reinterpret_cast<float4*>(&sAH[row][pc4]) = h;
            *reinterpret_cast<float4*>(&sAL[row][pc4]) = l;

            float4 w = pB[it];
            float4 hb = make_float4(tf32_hi(w.x), tf32_hi(w.y), tf32_hi(w.z), tf32_hi(w.w));
            float4 lb = make_float4(cvt_tf32(w.x - hb.x), cvt_tf32(w.y - hb.y),
                                    cvt_tf32(w.z - hb.z), cvt_tf32(w.w - hb.w));
            *reinterpret_cast<float4*>(&sBH[row][pc4]) = hb;
            *reinterpret_cast<float4*>(&sBL[row][pc4]) = lb;
        }
        __syncthreads();

        // prefetch next slab (overlaps MMA work below)
        if (s < 7) {
            const int sn = s + 1;
            const float* Asrc = Abase + (size_t)r0 * L_ + sn * 32;
            const float* Bsrc = Bbase + sn * 32;
#pragma unroll
            for (int it = 0; it < 4; it++) {
                pA[it] = *reinterpret_cast<const float4*>(Asrc + (prow + it * 16) * L_ + pc4);
                pB[it] = *reinterpret_cast<const float4*>(Bsrc + (prow + it * 16) * 512 + pc4);
            }
        }

#pragma unroll
        for (int k8 = 0; k8 < 4; k8++) {
            const int k = k8 * 8;
            uint32_t ah[2][4], al[2][4], bh[4][2], bl[4][2];
#pragma unroll
            for (int mi = 0; mi < 2; mi++) {
                int r = wm + mi * 16 + qr;
                ah[mi][0] = __float_as_uint(sAH[r    ][k + qc    ]);
                ah[mi][1] = __float_as_uint(sAH[r + 8][k + qc    ]);
                ah[mi][2] = __float_as_uint(sAH[r    ][k + qc + 4]);
                ah[mi][3] = __float_as_uint(sAH[r + 8][k + qc + 4]);
                al[mi][0] = __float_as_uint(sAL[r    ][k + qc    ]);
                al[mi][1] = __float_as_uint(sAL[r + 8][k + qc    ]);
                al[mi][2] = __float_as_uint(sAL[r    ][k + qc + 4]);
                al[mi][3] = __float_as_uint(sAL[r + 8][k + qc + 4]);
            }
#pragma unroll
            for (int ni = 0; ni < 4; ni++) {
                int n = wn + ni * 8 + qr;
                bh[ni][0] = __float_as_uint(sBH[n][k + qc    ]);
                bh[ni][1] = __float_as_uint(sBH[n][k + qc + 4]);
                bl[ni][0] = __float_as_uint(sBL[n][k + qc    ]);
                bl[ni][1] = __float_as_uint(sBL[n][k + qc + 4]);
            }
#pragma unroll
            for (int mi = 0; mi < 2; mi++)
#pragma unroll
                for (int ni = 0; ni < 4; ni++)
                    mma_16n8k8(acc[mi][ni], ah[mi], bh[ni]);
#pragma unroll
            for (int mi = 0; mi < 2; mi++)
#pragma unroll
                for (int ni = 0; ni < 4; ni++)
                    mma_16n8k8(acc[mi][ni], al[mi], bh[ni]);
#pragma unroll
            for (int mi = 0; mi < 2; mi++)
#pragma unroll
                for (int ni = 0; ni < 4; ni++)
                    mma_16n8k8(acc[mi][ni], ah[mi], bl[ni]);
        }
    }

    float* dst = g_part[z];
#pragma unroll
    for (int mi = 0; mi < 2; mi++) {
        int row = r0 + wm + mi * 16 + qr;
#pragma unroll
        for (int ni = 0; ni < 4; ni++) {
            int col = n0 + wn + ni * 8 + qc * 2;
            *reinterpret_cast<float2*>(dst + (size_t)row * L_ + col) =
                make_float2(acc[mi][ni][0], acc[mi][ni][1]);
            *reinterpret_cast<float2*>(dst + (size_t)(row + 8) * L_ + col) =
                make_float2(acc[mi][ni][2], acc[mi][ni][3]);
        }
    }
}

// ---------------------------------------------------------------------------
// Kernel E: out = relu(part0 + part1), vectorized float4. grid 1024 x 256.
// ---------------------------------------------------------------------------
__global__ void __launch_bounds__(256) k_cmb(float* __restrict__ out) {
    const int i = (blockIdx.x * 256 + threadIdx.x) * 4;
    float4 p = *reinterpret_cast<const float4*>(&g_part[0][i]);
    float4 q = *reinterpret_cast<const float4*>(&g_part[1][i]);
    float4 v = make_float4(fmaxf(p.x + q.x, 0.f), fmaxf(p.y + q.y, 0.f),
                           fmaxf(p.z + q.z, 0.f), fmaxf(p.w + q.w, 0.f));
    *reinterpret_cast<float4*>(out + i) = v;
}

// ---------------------------------------------------------------------------
extern "C" void kernel_launch(void* const* d_in, const int* in_sizes, int n_in,
                              void* d_out, int out_size) {
    const float* x     = (const float*)d_in[0];   // [32,128,256]
    const float* a     = (const float*)d_in[1];   // [128,128]
    const float* Theta = (const float*)d_in[2];   // [2,256,256]
    float* out = (float*)d_out;                   // [32,128,256]

    k_ttdiff <<<dim3(40, 32),    256>>>(x, Theta);
    k_nt     <<<256,             128>>>(a);
    k_y      <<<dim3(4, 4, 32),  128>>>(x);
    k_out_mma<<<dim3(4, 64, 2),  128>>>(x);
    k_cmb    <<<1024,            256>>>(out);
}

// round 10
// speedup vs baseline: 1.4522x; 1.1798x over previous
#include <cuda_runtime.h>
#include <cuda_bf16.h>
#include <cstdint>

#define B_  32
#define C_  128
#define L_  256
#define CC_ (C_ * C_)      // 16384
#define BCC_ (B_ * CC_)    // 524288

// Scratch (device globals — no allocations allowed)
__device__ float g_diff[BCC_];        // [b][i][j] pairwise L1
__device__ float g_tmpS[BCC_];        // exp(relu((1-diffn)*a))
__device__ float g_y[B_ * C_ * L_];   // adj^T x  (column-normalized)
__device__ float g_tt[256 * 512];     // B operand: [n][k] K-major, sign-folded

// ===========================================================================
// helpers
// ===========================================================================
// split (x,y) into packed bf16x2 hi + lo words (2-term split, 16 mantissa bits)
__device__ __forceinline__ void bf16_split2(float x, float y,
                                            uint32_t& hi, uint32_t& lo) {
    __nv_bfloat16 hx = __float2bfloat16(x);
    __nv_bfloat16 hy = __float2bfloat16(y);
    __nv_bfloat16 lx = __float2bfloat16(x - __bfloat162float(hx));
    __nv_bfloat16 ly = __float2bfloat16(y - __bfloat162float(hy));
    hi = (uint32_t)__bfloat16_as_ushort(hx) | ((uint32_t)__bfloat16_as_ushort(hy) << 16);
    lo = (uint32_t)__bfloat16_as_ushort(lx) | ((uint32_t)__bfloat16_as_ushort(ly) << 16);
}
__device__ __forceinline__ void mma_bf16(float c[4], const uint32_t a[4],
                                         const uint32_t b[2]) {
    asm volatile(
        "mma.sync.aligned.m16n8k16.row.col.f32.bf16.bf16.f32 "
        "{%0,%1,%2,%3}, {%4,%5,%6,%7}, {%8,%9}, {%0,%1,%2,%3};"
        : "+f"(c[0]), "+f"(c[1]), "+f"(c[2]), "+f"(c[3])
        : "r"(a[0]), "r"(a[1]), "r"(a[2]), "r"(a[3]), "r"(b[0]), "r"(b[1]));
}

// ---------------------------------------------------------------------------
// Kernel A (merged): blockIdx.x < 36  -> symmetric pairwise-L1 diff tile
//                    blockIdx.x >= 36 -> Theta transpose/sign-fold into g_tt
// grid (40, 32), 256 threads.
// ---------------------------------------------------------------------------
__global__ void __launch_bounds__(256) k_ttdiff(const float* __restrict__ x,
                                                const float* __restrict__ Theta) {
    __shared__ float sxi[16][260];
    __shared__ float sxj[16][260];

    if (blockIdx.x >= 36) {
        __shared__ float t[32][33];
        const int id = (blockIdx.x - 36) * 32 + blockIdx.y;   // 0..127
        const int kt = (id >> 3) * 32, nt = (id & 7) * 32;
        const int tx = threadIdx.x & 31, ty = threadIdx.x >> 5;  // ty 0..7
#pragma unroll
        for (int r = 0; r < 32; r += 8) {
            int k = kt + ty + r;
            int n = nt + tx;
            float v = (k < 256) ? Theta[k * 256 + n]
                                : -Theta[65536 + (k - 256) * 256 + n];
            t[ty + r][tx] = v;
        }
        __syncthreads();
#pragma unroll
        for (int r = 0; r < 32; r += 8) {
            int n = nt + ty + r;
            int k = kt + tx;
            g_tt[n * 512 + k] = t[tx][ty + r];
        }
        return;
    }

    const int b = blockIdx.y;
    int rem = blockIdx.x, ti = 0;
    while (rem >= 8 - ti) { rem -= 8 - ti; ti++; }
    const int tj = ti + rem;
    const int i0 = ti * 16, j0 = tj * 16;

    const int tid = threadIdx.x;
    const float* xb = x + b * C_ * L_;

#pragma unroll
    for (int rep = 0; rep < 4; rep++) {
        int idx = rep * 256 + tid;
        int row = idx >> 6, c4 = (idx & 63) * 4;
        *reinterpret_cast<float4*>(&sxi[row][c4]) =
            *reinterpret_cast<const float4*>(xb + (i0 + row) * L_ + c4);
        *reinterpret_cast<float4*>(&sxj[row][c4]) =
            *reinterpret_cast<const float4*>(xb + (j0 + row) * L_ + c4);
    }
    __syncthreads();

    const int ii = tid >> 4, jj = tid & 15;
    const float* ri = &sxi[ii][0];
    const float* rj = &sxj[jj][0];

    float a0 = 0.f, a1 = 0.f, a2 = 0.f, a3 = 0.f;
#pragma unroll
    for (int l = 0; l < L_; l += 16) {
        float4 u0 = *reinterpret_cast<const float4*>(ri + l);
        float4 v0 = *reinterpret_cast<const float4*>(rj + l);
        float4 u1 = *reinterpret_cast<const float4*>(ri + l + 4);
        float4 v1 = *reinterpret_cast<const float4*>(rj + l + 4);
        float4 u2 = *reinterpret_cast<const float4*>(ri + l + 8);
        float4 v2 = *reinterpret_cast<const float4*>(rj + l + 8);
        float4 u3 = *reinterpret_cast<const float4*>(ri + l + 12);
        float4 v3 = *reinterpret_cast<const float4*>(rj + l + 12);
        a0 += fabsf(u0.x - v0.x) + fabsf(u0.y - v0.y)
            + fabsf(u0.z - v0.z) + fabsf(u0.w - v0.w);
        a1 += fabsf(u1.x - v1.x) + fabsf(u1.y - v1.y)
            + fabsf(u1.z - v1.z) + fabsf(u1.w - v1.w);
        a2 += fabsf(u2.x - v2.x) + fabsf(u2.y - v2.y)
            + fabsf(u2.z - v2.z) + fabsf(u2.w - v2.w);
        a3 += fabsf(u3.x - v3.x) + fabsf(u3.y - v3.y)
            + fabsf(u3.z - v3.z) + fabsf(u3.w - v3.w);
    }
    float res = (a0 + a1) + (a2 + a3);

    g_diff[b * CC_ + (i0 + ii) * C_ + (j0 + jj)] = res;
    if (ti != tj)
        g_diff[b * CC_ + (j0 + jj) * C_ + (i0 + ii)] = res;
}

// ---------------------------------------------------------------------------
// Kernel B (fused norm+tmps): 2 threads per (i,j) pair, b split 16/16,
// shfl_xor combine. grid 256 x 128 threads.
// ---------------------------------------------------------------------------
__global__ void __launch_bounds__(128) k_nt(const float* __restrict__ a) {
    const int g  = blockIdx.x * 128 + threadIdx.x;
    const int ij = g >> 1;
    const int h  = g & 1;
    const int b0 = h * 16;

    float d[16];
#pragma unroll
    for (int bb = 0; bb < 16; bb++) d[bb] = g_diff[(b0 + bb) * CC_ + ij];

    float ss = 0.f;
#pragma unroll
    for (int bb = 0; bb < 16; bb++) ss += d[bb] * d[bb];
    ss += __shfl_xor_sync(0xFFFFFFFFu, ss, 1);

    const float rn  = 1.f / fmaxf(sqrtf(ss), 1e-12f);
    const float aij = a[ij];

#pragma unroll
    for (int bb = 0; bb < 16; bb++) {
        float v = __expf(fmaxf((1.f - d[bb] * rn) * aij, 0.f));
        g_tmpS[(b0 + bb) * CC_ + ij] = v;
    }
}

// ---------------------------------------------------------------------------
// Kernel C: y[b,j,l] = (1/cs[b,j]) * sum_i tmpS[b,i,j] * x[b,i,l]
// Column sums computed in-kernel. grid (4 l, 4 j, 32 b), 128 threads.
// ---------------------------------------------------------------------------
__global__ void k_y(const float* __restrict__ x) {
    __shared__ float sS[16][32];
    __shared__ float sX[16][64];
    __shared__ float srcs[32];
    const int b  = blockIdx.z;
    const int j0 = blockIdx.y * 32;
    const int l0 = blockIdx.x * 64;
    const int tid = threadIdx.x;
    const int tx = tid & 15, ty = tid >> 4;  // ty 0..7

    float acc[4][4];
#pragma unroll
    for (int r = 0; r < 4; r++)
#pragma unroll
        for (int c = 0; c < 4; c++) acc[r][c] = 0.f;
    float csum = 0.f;

    const float* Sb = g_tmpS + b * CC_;
    const float* Xb = x + b * C_ * L_;

#pragma unroll 1
    for (int i0 = 0; i0 < C_; i0 += 16) {
        __syncthreads();
#pragma unroll
        for (int rep = 0; rep < 4; rep++) {
            int idx = rep * 128 + tid;
            int r = idx >> 5, c = idx & 31;
            sS[r][c] = Sb[(i0 + r) * C_ + j0 + c];
        }
#pragma unroll
        for (int rep = 0; rep < 8; rep++) {
            int idx = rep * 128 + tid;
            int r = idx >> 6, c = idx & 63;
            sX[r][c] = Xb[(i0 + r) * L_ + l0 + c];
        }
        __syncthreads();
        if (tid < 32) {
#pragma unroll
            for (int r = 0; r < 16; r++) csum += sS[r][tid];
        }
#pragma unroll
        for (int i = 0; i < 16; i++) {
            float4 av = *reinterpret_cast<const float4*>(&sS[i][ty * 4]);
            float4 bv = *reinterpret_cast<const float4*>(&sX[i][tx * 4]);
            float a4[4] = {av.x, av.y, av.z, av.w};
            float b4[4] = {bv.x, bv.y, bv.z, bv.w};
#pragma unroll
            for (int r = 0; r < 4; r++)
#pragma unroll
                for (int c = 0; c < 4; c++)
                    acc[r][c] += a4[r] * b4[c];
        }
    }
    if (tid < 32) srcs[tid] = 1.f / csum;
    __syncthreads();

#pragma unroll
    for (int r = 0; r < 4; r++) {
        int jj = j0 + ty * 4 + r;
        float rc = srcs[ty * 4 + r];
        float4 v = make_float4(acc[r][0] * rc, acc[r][1] * rc,
                               acc[r][2] * rc, acc[r][3] * rc);
        *reinterpret_cast<float4*>(&g_y[b * C_ * L_ + jj * L_ + l0 + tx * 4]) = v;
    }
}

// ---------------------------------------------------------------------------
// Kernel D (tensor core, mma.sync bf16 m16n8k16, 3-product 2-term split):
//   out = relu( [x | g_y] @ g_tt^T ),  M=4096, N=256, K=512
// CTA: 64x64 tile, 128 threads (4 warps 2x2, warp 32x32). grid (4 n, 64 m).
// smem holds packed bf16x2 words [row][k2], stride 20 words (conflict-free).
// Per 32-k slab: 2 k16 steps x 24 MMA = 48 MMA (half of tf32x3 design).
// Register prefetch of next slab overlaps MMA work.
// ---------------------------------------------------------------------------
__global__ void __launch_bounds__(128) k_out_mma(const float* __restrict__ x,
                                                 float* __restrict__ out) {
    __shared__ uint32_t sAH[64][20], sAL[64][20];
    __shared__ uint32_t sBH[64][20], sBL[64][20];

    const int tid  = threadIdx.x;
    const int lane = tid & 31, wid = tid >> 5;
    const int n0 = blockIdx.x * 64;
    const int r0 = blockIdx.y * 64;
    const int wm = (wid >> 1) * 32;
    const int wn = (wid & 1) * 32;
    const int qr = lane >> 2;         // groupID 0..7
    const int qc = lane & 3;          // threadID-in-group 0..3
    const int prow = tid >> 3, pc4 = (tid & 7) * 4;
    const int pw = pc4 >> 1;          // word index (even)

    float acc[2][4][4];
#pragma unroll
    for (int mi = 0; mi < 2; mi++)
#pragma unroll
        for (int ni = 0; ni < 4; ni++)
#pragma unroll
            for (int e = 0; e < 4; e++) acc[mi][ni][e] = 0.f;

    // prefetch slab 0
    float4 pA[4], pB[4];
    {
        const float* Asrc = x + (size_t)r0 * L_;
        const float* Bsrc = g_tt + (size_t)n0 * 512;
#pragma unroll
        for (int it = 0; it < 4; it++) {
            pA[it] = *reinterpret_cast<const float4*>(Asrc + (prow + it * 16) * L_ + pc4);
            pB[it] = *reinterpret_cast<const float4*>(Bsrc + (prow + it * 16) * 512 + pc4);
        }
    }

#pragma unroll 1
    for (int s = 0; s < 16; s++) {
        __syncthreads();
        // hand current slab to smem: bf16 2-term split, packed x2 words
#pragma unroll
        for (int it = 0; it < 4; it++) {
            int row = prow + it * 16;
            float4 v = pA[it];
            uint32_t h0, l0, h1, l1;
            bf16_split2(v.x, v.y, h0, l0);
            bf16_split2(v.z, v.w, h1, l1);
            *reinterpret_cast<uint2*>(&sAH[row][pw]) = make_uint2(h0, h1);
            *reinterpret_cast<uint2*>(&sAL[row][pw]) = make_uint2(l0, l1);

            float4 w = pB[it];
            uint32_t g0, m0, g1, m1;
            bf16_split2(w.x, w.y, g0, m0);
            bf16_split2(w.z, w.w, g1, m1);
            *reinterpret_cast<uint2*>(&sBH[row][pw]) = make_uint2(g0, g1);
            *reinterpret_cast<uint2*>(&sBL[row][pw]) = make_uint2(m0, m1);
        }
        __syncthreads();

        // prefetch next slab (overlaps MMA work below)
        if (s < 15) {
            const int sn = s + 1;
            const float* Asrc = (sn < 8) ? (x   + (size_t)r0 * L_ + sn * 32)
                                         : (g_y + (size_t)r0 * L_ + (sn - 8) * 32);
            const float* Bsrc = g_tt + (size_t)n0 * 512 + sn * 32;
#pragma unroll
            for (int it = 0; it < 4; it++) {
                pA[it] = *reinterpret_cast<const float4*>(Asrc + (prow + it * 16) * L_ + pc4);
                pB[it] = *reinterpret_cast<const float4*>(Bsrc + (prow + it * 16) * 512 + pc4);
            }
        }

        // 2 k16 steps per slab
#pragma unroll
        for (int t = 0; t < 2; t++) {
            const int k2 = t * 8;
            uint32_t ah[2][4], al[2][4], bh[4][2], bl[4][2];
#pragma unroll
            for (int mi = 0; mi < 2; mi++) {
                int r = wm + mi * 16 + qr;
                ah[mi][0] = sAH[r    ][k2 + qc];
                ah[mi][1] = sAH[r + 8][k2 + qc];
                ah[mi][2] = sAH[r    ][k2 + qc + 4];
                ah[mi][3] = sAH[r + 8][k2 + qc + 4];
                al[mi][0] = sAL[r    ][k2 + qc];
                al[mi][1] = sAL[r + 8][k2 + qc];
                al[mi][2] = sAL[r    ][k2 + qc + 4];
                al[mi][3] = sAL[r + 8][k2 + qc + 4];
            }
#pragma unroll
            for (int ni = 0; ni < 4; ni++) {
                int n = wn + ni * 8 + qr;
                bh[ni][0] = sBH[n][k2 + qc];
                bh[ni][1] = sBH[n][k2 + qc + 4];
                bl[ni][0] = sBL[n][k2 + qc];
                bl[ni][1] = sBL[n][k2 + qc + 4];
            }
#pragma unroll
            for (int mi = 0; mi < 2; mi++)
#pragma unroll
                for (int ni = 0; ni < 4; ni++)
                    mma_bf16(acc[mi][ni], ah[mi], bh[ni]);
#pragma unroll
            for (int mi = 0; mi < 2; mi++)
#pragma unroll
                for (int ni = 0; ni < 4; ni++)
                    mma_bf16(acc[mi][ni], al[mi], bh[ni]);
#pragma unroll
            for (int mi = 0; mi < 2; mi++)
#pragma unroll
                for (int ni = 0; ni < 4; ni++)
                    mma_bf16(acc[mi][ni], ah[mi], bl[ni]);
        }
    }

    // epilogue: relu + store
#pragma unroll
    for (int mi = 0; mi < 2; mi++) {
        int row = r0 + wm + mi * 16 + qr;
#pragma unroll
        for (int ni = 0; ni < 4; ni++) {
            int col = n0 + wn + ni * 8 + qc * 2;
            float2 v0 = make_float2(fmaxf(acc[mi][ni][0], 0.f),
                                    fmaxf(acc[mi][ni][1], 0.f));
            float2 v1 = make_float2(fmaxf(acc[mi][ni][2], 0.f),
                                    fmaxf(acc[mi][ni][3], 0.f));
            *reinterpret_cast<float2*>(out + (size_t)row * L_ + col) = v0;
            *reinterpret_cast<float2*>(out + (size_t)(row + 8) * L_ + col) = v1;
        }
    }
}

// ---------------------------------------------------------------------------
extern "C" void kernel_launch(void* const* d_in, const int* in_sizes, int n_in,
                              void* d_out, int out_size) {
    const float* x     = (const float*)d_in[0];   // [32,128,256]
    const float* a     = (const float*)d_in[1];   // [128,128]
    const float* Theta = (const float*)d_in[2];   // [2,256,256]
    float* out = (float*)d_out;                   // [32,128,256]

    k_ttdiff <<<dim3(40, 32),   256>>>(x, Theta);
    k_nt     <<<256,            128>>>(a);
    k_y      <<<dim3(4, 4, 32), 128>>>(x);
    k_out_mma<<<dim3(4, 64),    128>>>(x, out);
}